// round 5
// baseline (speedup 1.0000x reference)
#include <cuda_runtime.h>
#include <cuda_bf16.h>
#include <cstdint>

#define BB 16384
#define FF 50
#define EE 64

// Scratch for the stage-1 intermediate h_out [B,F,E] (~210MB).
__device__ float g_ho[(size_t)BB * FF * EE];

// ======================= helpers =======================
__device__ __forceinline__ uint32_t smem_u32(const void* p) {
    uint32_t a;
    asm("{ .reg .u64 t; cvta.to.shared.u64 t, %1; cvt.u32.u64 %0, t; }"
        : "=r"(a) : "l"(p));
    return a;
}
__device__ __forceinline__ void ldsm4(uint32_t* r, uint32_t a) {
    asm volatile("ldmatrix.sync.aligned.m8n8.x4.shared.b16 {%0,%1,%2,%3}, [%4];"
        : "=r"(r[0]), "=r"(r[1]), "=r"(r[2]), "=r"(r[3]) : "r"(a));
}
__device__ __forceinline__ void ldsm4t(uint32_t* r, uint32_t a) {
    asm volatile("ldmatrix.sync.aligned.m8n8.x4.trans.shared.b16 {%0,%1,%2,%3}, [%4];"
        : "=r"(r[0]), "=r"(r[1]), "=r"(r[2]), "=r"(r[3]) : "r"(a));
}
__device__ __forceinline__ void mma16816(float* d, const uint32_t* a,
                                         uint32_t b0, uint32_t b1) {
    asm volatile(
        "mma.sync.aligned.m16n8k16.row.col.f32.bf16.bf16.f32 "
        "{%0,%1,%2,%3}, {%4,%5,%6,%7}, {%8,%9}, {%0,%1,%2,%3};"
        : "+f"(d[0]), "+f"(d[1]), "+f"(d[2]), "+f"(d[3])
        : "r"(a[0]), "r"(a[1]), "r"(a[2]), "r"(a[3]), "r"(b0), "r"(b1));
}

// Convert float4 -> bf16 hi/lo, store into [row][64]bf16 tile (128B rows,
// XOR-(row&7)<<4 permuted so ldmatrix over 8 consecutive rows is conflict-free).
__device__ __forceinline__ void split_store4(char* hiB, char* loB, int row, int c4,
                                             float4 v) {
    __nv_bfloat16 h0 = __float2bfloat16_rn(v.x);
    __nv_bfloat16 h1 = __float2bfloat16_rn(v.y);
    __nv_bfloat16 h2 = __float2bfloat16_rn(v.z);
    __nv_bfloat16 h3 = __float2bfloat16_rn(v.w);
    __nv_bfloat16 l0 = __float2bfloat16_rn(v.x - __bfloat162float(h0));
    __nv_bfloat16 l1 = __float2bfloat16_rn(v.y - __bfloat162float(h1));
    __nv_bfloat16 l2 = __float2bfloat16_rn(v.z - __bfloat162float(h2));
    __nv_bfloat16 l3 = __float2bfloat16_rn(v.w - __bfloat162float(h3));
    __nv_bfloat162 hp0 = __nv_bfloat162(h0, h1), hp1 = __nv_bfloat162(h2, h3);
    __nv_bfloat162 lp0 = __nv_bfloat162(l0, l1), lp1 = __nv_bfloat162(l2, l3);
    uint32_t byte0 = (uint32_t)(row * 128 + c4 * 8);
    uint32_t sw = byte0 ^ (((uint32_t)row & 7u) << 4);
    *reinterpret_cast<uint32_t*>(hiB + sw)     = *reinterpret_cast<uint32_t*>(&hp0);
    *reinterpret_cast<uint32_t*>(hiB + sw + 4) = *reinterpret_cast<uint32_t*>(&hp1);
    *reinterpret_cast<uint32_t*>(loB + sw)     = *reinterpret_cast<uint32_t*>(&lp0);
    *reinterpret_cast<uint32_t*>(loB + sw + 4) = *reinterpret_cast<uint32_t*>(&lp1);
}

// ============================================================================
// Stage 1 / Stage 3: per-field GEMM via mma.sync bf16-split.
//   Y[b,i] = sum_j X[b,j] * W[f,i,j]  (+bias[i])
// Grid (B/128, F), 128 threads (4 warps). CTA tile 128b x 64i, K=64.
// Warp w: rows 32w..32w+31 (two m16 tiles) x all 64 i (8 n-tiles).
// ADD_BIAS variant is IN-PLACE on d_out (X fully staged to smem first;
// CTAs own disjoint (b-tile, f) regions).
// ============================================================================
#define GX_HI 0
#define GX_LO 16384
#define GW_HI 32768
#define GW_LO 40960
#define G_BIAS 49152
#define G_SMEM 49664

template <bool ADD_BIAS>
__global__ __launch_bounds__(128, 4) void field_gemm_mma(
    const float* __restrict__ X, const float* __restrict__ W,
    const float* __restrict__ bias, float* __restrict__ Y) {
    extern __shared__ char smem[];
    const uint32_t sb = smem_u32(smem);
    const int tid = threadIdx.x, w = tid >> 5, l = tid & 31;
    const int f = blockIdx.y, b0 = blockIdx.x * 128;

    if (ADD_BIAS && tid < 16)
        reinterpret_cast<float4*>(smem + G_BIAS)[tid] =
            reinterpret_cast<const float4*>(bias)[tid];

    // Stage X tile (128 x 64 fp32) -> bf16 hi/lo
    const float* Xb = X + (size_t)b0 * (FF * EE) + (size_t)f * EE;
#pragma unroll
    for (int t = 0; t < 16; t++) {
        int idx = tid + t * 128;
        int b = idx >> 4, c4 = idx & 15;
        float4 v = *reinterpret_cast<const float4*>(Xb + (size_t)b * (FF * EE) + c4 * 4);
        split_store4(smem + GX_HI, smem + GX_LO, b, c4, v);
    }
    // Stage W[f] (64 x 64): rows are n=i, k=j contiguous (exactly what mma needs)
    const float* Wf = W + (size_t)f * EE * EE;
#pragma unroll
    for (int t = 0; t < 8; t++) {
        int idx = tid + t * 128;
        int n = idx >> 4, c4 = idx & 15;
        float4 v = *reinterpret_cast<const float4*>(Wf + n * EE + c4 * 4);
        split_store4(smem + GW_HI, smem + GW_LO, n, c4, v);
    }
    __syncthreads();

    // lane geometry for ldmatrix
    const int arow0 = w * 32 + (l & 15);       // A: rows m..m+15, x4 = 16x16
    const int achk  = l >> 4;                  // k-chunk select (0/1)
    const int brow  = (l & 7) + ((l >> 4) << 3);  // B: rows n..n+15
    const int bchk  = (l >> 3) & 1;

    float D[2][8][4] = {};

#pragma unroll
    for (int ks = 0; ks < 4; ks++) {
        uint32_t Ahi[2][4], Alo[2][4];
#pragma unroll
        for (int mt = 0; mt < 2; mt++) {
            int row = arow0 + mt * 16;
            uint32_t off = (uint32_t)(row * 128) +
                           ((uint32_t)((2 * ks + achk) ^ (row & 7)) << 4);
            ldsm4(Ahi[mt], sb + GX_HI + off);
            ldsm4(Alo[mt], sb + GX_LO + off);
        }
#pragma unroll
        for (int p = 0; p < 4; p++) {
            int nrow = p * 16 + brow;
            uint32_t off = (uint32_t)(nrow * 128) +
                           ((uint32_t)((2 * ks + bchk) ^ (nrow & 7)) << 4);
            uint32_t Bhi[4], Blo[4];
            ldsm4(Bhi, sb + GW_HI + off);
            ldsm4(Blo, sb + GW_LO + off);
#pragma unroll
            for (int mt = 0; mt < 2; mt++) {
                mma16816(D[mt][2 * p],     Ahi[mt], Bhi[0], Bhi[1]);
                mma16816(D[mt][2 * p],     Ahi[mt], Blo[0], Blo[1]);
                mma16816(D[mt][2 * p],     Alo[mt], Bhi[0], Bhi[1]);
                mma16816(D[mt][2 * p + 1], Ahi[mt], Bhi[2], Bhi[3]);
                mma16816(D[mt][2 * p + 1], Ahi[mt], Blo[2], Blo[3]);
                mma16816(D[mt][2 * p + 1], Alo[mt], Bhi[2], Bhi[3]);
            }
        }
    }

    const float* bsm = reinterpret_cast<const float*>(smem + G_BIAS);
    const int r0 = l >> 2, c0 = (l & 3) * 2;
#pragma unroll
    for (int mt = 0; mt < 2; mt++) {
#pragma unroll
        for (int half = 0; half < 2; half++) {
            int row = b0 + w * 32 + mt * 16 + r0 + half * 8;
            float* yrow = Y + (size_t)row * (FF * EE) + (size_t)f * EE;
#pragma unroll
            for (int nt = 0; nt < 8; nt++) {
                float2 v = make_float2(D[mt][nt][2 * half], D[mt][nt][2 * half + 1]);
                if (ADD_BIAS) {
                    v.x += bsm[nt * 8 + c0];
                    v.y += bsm[nt * 8 + c0 + 1];
                }
                *reinterpret_cast<float2*>(yrow + nt * 8 + c0) = v;
            }
        }
    }
}

// ============================================================================
// Stage 2: aggregation via mma.sync bf16-split.
//   out[b,f,e] = sum_g G[b,f,g] * HO[b,g,e]   ([50x50]@[50x64], padded to 64)
// 2 batches per CTA, 256 threads (4 warps per batch, each warp = one m16 tile).
// A = G (rows f, k=g contiguous -> plain ldmatrix). B = HO ([g][e] rows ->
// ldmatrix.trans gives B[k=g][n=e] fragments). Pads zero-filled.
// ============================================================================
#define AG_HI(lb) ((lb) * 32768 + 0)
#define AG_LO(lb) ((lb) * 32768 + 8192)
#define AH_HI(lb) ((lb) * 32768 + 16384)
#define AH_LO(lb) ((lb) * 32768 + 24576)
#define A_SMEM 65536

__global__ __launch_bounds__(256, 2) void aggr_mma(
    const float* __restrict__ Gm, const float* __restrict__ HO,
    float* __restrict__ out) {
    extern __shared__ char smem[];
    const uint32_t sb = smem_u32(smem);
    const int tid = threadIdx.x, w = tid >> 5, l = tid & 31;
    const int b0 = blockIdx.x * 2;

    // zero everything (pads must be 0)
#pragma unroll
    for (int t = 0; t < 16; t++)
        reinterpret_cast<float4*>(smem)[tid + t * 256] = make_float4(0.f, 0.f, 0.f, 0.f);
    __syncthreads();

    // fill G: [f<50][g<50] -> bf16 hi/lo, rows 128B, swizzled
    for (int idx = tid; idx < 2 * FF * FF; idx += 256) {
        int lb = (idx >= FF * FF);
        int r = idx - lb * (FF * FF);
        int fq = r / FF, gq = r - fq * FF;
        float v = Gm[(size_t)(b0 + lb) * (FF * FF) + r];
        __nv_bfloat16 hv = __float2bfloat16_rn(v);
        __nv_bfloat16 lv = __float2bfloat16_rn(v - __bfloat162float(hv));
        uint32_t sw = (uint32_t)(fq * 128 + gq * 2) ^ (((uint32_t)fq & 7u) << 4);
        *reinterpret_cast<__nv_bfloat16*>(smem + AG_HI(lb) + sw) = hv;
        *reinterpret_cast<__nv_bfloat16*>(smem + AG_LO(lb) + sw) = lv;
    }
    // fill HO: [g<50][e 64]
    for (int idx = tid; idx < 2 * FF * 16; idx += 256) {
        int lb = (idx >= FF * 16);
        int r = idx - lb * (FF * 16);
        int g = r >> 4, c4 = r & 15;
        float4 v = *reinterpret_cast<const float4*>(
            HO + (size_t)(b0 + lb) * (FF * EE) + r * 4);
        split_store4(smem + AH_HI(lb), smem + AH_LO(lb), g, c4, v);
    }
    __syncthreads();

    const int lb = w >> 2, wq = w & 3;
    const int arow  = wq * 16 + (l & 15);
    const int achk  = l >> 4;
    const int bkrow = (l & 7) + (((l >> 3) & 1) << 3);
    const int bchk  = l >> 4;

    float D[8][4] = {};

#pragma unroll
    for (int ks = 0; ks < 4; ks++) {
        uint32_t Ahi[4], Alo[4];
        uint32_t aoff = (uint32_t)(arow * 128) +
                        ((uint32_t)((2 * ks + achk) ^ (arow & 7)) << 4);
        ldsm4(Ahi, sb + AG_HI(lb) + aoff);
        ldsm4(Alo, sb + AG_LO(lb) + aoff);
#pragma unroll
        for (int p = 0; p < 4; p++) {
            int krow = ks * 16 + bkrow;
            uint32_t boff = (uint32_t)(krow * 128) +
                            ((uint32_t)((2 * p + bchk) ^ (krow & 7)) << 4);
            uint32_t Bhi[4], Blo[4];
            ldsm4t(Bhi, sb + AH_HI(lb) + boff);
            ldsm4t(Blo, sb + AH_LO(lb) + boff);
            mma16816(D[2 * p],     Ahi, Bhi[0], Bhi[1]);
            mma16816(D[2 * p],     Ahi, Blo[0], Blo[1]);
            mma16816(D[2 * p],     Alo, Bhi[0], Bhi[1]);
            mma16816(D[2 * p + 1], Ahi, Bhi[2], Bhi[3]);
            mma16816(D[2 * p + 1], Ahi, Blo[2], Blo[3]);
            mma16816(D[2 * p + 1], Alo, Bhi[2], Bhi[3]);
        }
    }

    const int r0 = l >> 2, c0 = (l & 3) * 2;
#pragma unroll
    for (int half = 0; half < 2; half++) {
        int frow = wq * 16 + r0 + half * 8;
        if (frow < FF) {
            float* orow = out + (size_t)(b0 + lb) * (FF * EE) + frow * EE;
#pragma unroll
            for (int nt = 0; nt < 8; nt++)
                *reinterpret_cast<float2*>(orow + nt * 8 + c0) =
                    make_float2(D[nt][2 * half], D[nt][2 * half + 1]);
        }
    }
}

extern "C" void kernel_launch(void* const* d_in, const int* in_sizes, int n_in,
                              void* d_out, int out_size) {
    const float* g     = (const float*)d_in[0];   // [B,F,F]
    const float* h     = (const float*)d_in[1];   // [B,F,E]
    const float* W_in  = (const float*)d_in[2];   // [F,E,E]
    const float* W_out = (const float*)d_in[3];   // [F,E,E]
    const float* bias  = (const float*)d_in[4];   // [E]
    float* out = (float*)d_out;                   // [B,F,E]

    float* ho = nullptr;
    cudaGetSymbolAddress((void**)&ho, g_ho);

    cudaFuncSetAttribute((const void*)field_gemm_mma<false>,
                         cudaFuncAttributeMaxDynamicSharedMemorySize, G_SMEM);
    cudaFuncSetAttribute((const void*)field_gemm_mma<true>,
                         cudaFuncAttributeMaxDynamicSharedMemorySize, G_SMEM);
    cudaFuncSetAttribute((const void*)aggr_mma,
                         cudaFuncAttributeMaxDynamicSharedMemorySize, A_SMEM);

    // Stage 1: ho = einsum('fij,bfj->bfi', W_out, h)
    field_gemm_mma<false><<<dim3(BB / 128, FF), 128, G_SMEM>>>(h, W_out, nullptr, ho);
    // Stage 2: out = einsum('bfg,bge->bfe', g, ho)
    aggr_mma<<<BB / 2, 256, A_SMEM>>>(g, ho, out);
    // Stage 3 (in-place): out = einsum('fij,bfj->bfi', W_in, out) + bias
    field_gemm_mma<true><<<dim3(BB / 128, FF), 128, G_SMEM>>>(out, W_in, bias, out);
}

// round 6
// speedup vs baseline: 1.3677x; 1.3677x over previous
#include <cuda_runtime.h>
#include <cuda_bf16.h>
#include <cstdint>

#define BB 16384
#define FF 50
#define EE 64

// Stage-1 intermediate h_out, stored as bf16 hi/lo split (105MB each).
__device__ __nv_bfloat16 g_ho_hi[(size_t)BB * FF * EE];
__device__ __nv_bfloat16 g_ho_lo[(size_t)BB * FF * EE];

// ======================= helpers =======================
__device__ __forceinline__ uint32_t smem_u32(const void* p) {
    uint32_t a;
    asm("{ .reg .u64 t; cvta.to.shared.u64 t, %1; cvt.u32.u64 %0, t; }"
        : "=r"(a) : "l"(p));
    return a;
}
__device__ __forceinline__ void ldsm4(uint32_t* r, uint32_t a) {
    asm volatile("ldmatrix.sync.aligned.m8n8.x4.shared.b16 {%0,%1,%2,%3}, [%4];"
        : "=r"(r[0]), "=r"(r[1]), "=r"(r[2]), "=r"(r[3]) : "r"(a));
}
__device__ __forceinline__ void ldsm4t(uint32_t* r, uint32_t a) {
    asm volatile("ldmatrix.sync.aligned.m8n8.x4.trans.shared.b16 {%0,%1,%2,%3}, [%4];"
        : "=r"(r[0]), "=r"(r[1]), "=r"(r[2]), "=r"(r[3]) : "r"(a));
}
__device__ __forceinline__ void mma16816(float* d, const uint32_t* a,
                                         uint32_t b0, uint32_t b1) {
    asm volatile(
        "mma.sync.aligned.m16n8k16.row.col.f32.bf16.bf16.f32 "
        "{%0,%1,%2,%3}, {%4,%5,%6,%7}, {%8,%9}, {%0,%1,%2,%3};"
        : "+f"(d[0]), "+f"(d[1]), "+f"(d[2]), "+f"(d[3])
        : "r"(a[0]), "r"(a[1]), "r"(a[2]), "r"(a[3]), "r"(b0), "r"(b1));
}

// Convert float4 -> bf16 hi/lo, store into [row][64]bf16 tile (128B rows,
// XOR-(row&7)<<4 permuted so ldmatrix over 8 consecutive rows is conflict-free).
__device__ __forceinline__ void split_store4(char* hiB, char* loB, int row, int c4,
                                             float4 v) {
    __nv_bfloat16 h0 = __float2bfloat16_rn(v.x);
    __nv_bfloat16 h1 = __float2bfloat16_rn(v.y);
    __nv_bfloat16 h2 = __float2bfloat16_rn(v.z);
    __nv_bfloat16 h3 = __float2bfloat16_rn(v.w);
    __nv_bfloat16 l0 = __float2bfloat16_rn(v.x - __bfloat162float(h0));
    __nv_bfloat16 l1 = __float2bfloat16_rn(v.y - __bfloat162float(h1));
    __nv_bfloat16 l2 = __float2bfloat16_rn(v.z - __bfloat162float(h2));
    __nv_bfloat16 l3 = __float2bfloat16_rn(v.w - __bfloat162float(h3));
    __nv_bfloat162 hp0 = __nv_bfloat162(h0, h1), hp1 = __nv_bfloat162(h2, h3);
    __nv_bfloat162 lp0 = __nv_bfloat162(l0, l1), lp1 = __nv_bfloat162(l2, l3);
    uint32_t byte0 = (uint32_t)(row * 128 + c4 * 8);
    uint32_t sw = byte0 ^ (((uint32_t)row & 7u) << 4);
    *reinterpret_cast<uint32_t*>(hiB + sw)     = *reinterpret_cast<uint32_t*>(&hp0);
    *reinterpret_cast<uint32_t*>(hiB + sw + 4) = *reinterpret_cast<uint32_t*>(&hp1);
    *reinterpret_cast<uint32_t*>(loB + sw)     = *reinterpret_cast<uint32_t*>(&lp0);
    *reinterpret_cast<uint32_t*>(loB + sw + 4) = *reinterpret_cast<uint32_t*>(&lp1);
}

// ============================================================================
// Stage 1 / Stage 3: per-field GEMM via mma.sync bf16-split.
//   Y[b,i] = sum_j X[b,j] * W[f,i,j]
// MODE 0: write bf16 hi/lo split (stage 1 -> feeds aggr with zero conversion).
// MODE 1: write fp32 + bias, IN-PLACE on d_out (stage 3).
// Grid (B/128, F), 128 threads (4 warps). CTA tile 128b x 64i, K=64.
// ============================================================================
#define GX_HI 0
#define GX_LO 16384
#define GW_HI 32768
#define GW_LO 40960
#define G_BIAS 49152
#define G_SMEM 49664

template <int MODE>
__global__ __launch_bounds__(128, 4) void field_gemm_mma(
    const float* __restrict__ X, const float* __restrict__ W,
    const float* __restrict__ bias, float* __restrict__ Yf,
    __nv_bfloat16* __restrict__ Yhi, __nv_bfloat16* __restrict__ Ylo) {
    extern __shared__ char smem[];
    const uint32_t sb = smem_u32(smem);
    const int tid = threadIdx.x, w = tid >> 5, l = tid & 31;
    const int f = blockIdx.y, b0 = blockIdx.x * 128;

    if (MODE == 1 && tid < 16)
        reinterpret_cast<float4*>(smem + G_BIAS)[tid] =
            reinterpret_cast<const float4*>(bias)[tid];

    // Stage X tile (128 x 64 fp32) -> bf16 hi/lo
    const float* Xb = X + (size_t)b0 * (FF * EE) + (size_t)f * EE;
#pragma unroll
    for (int t = 0; t < 16; t++) {
        int idx = tid + t * 128;
        int b = idx >> 4, c4 = idx & 15;
        float4 v = *reinterpret_cast<const float4*>(Xb + (size_t)b * (FF * EE) + c4 * 4);
        split_store4(smem + GX_HI, smem + GX_LO, b, c4, v);
    }
    // Stage W[f] (64 x 64): rows are n=i, k=j contiguous
    const float* Wf = W + (size_t)f * EE * EE;
#pragma unroll
    for (int t = 0; t < 8; t++) {
        int idx = tid + t * 128;
        int n = idx >> 4, c4 = idx & 15;
        float4 v = *reinterpret_cast<const float4*>(Wf + n * EE + c4 * 4);
        split_store4(smem + GW_HI, smem + GW_LO, n, c4, v);
    }
    __syncthreads();

    const int arow0 = w * 32 + (l & 15);
    const int achk  = l >> 4;
    const int brow  = (l & 7) + ((l >> 4) << 3);
    const int bchk  = (l >> 3) & 1;

    float D[2][8][4] = {};

#pragma unroll
    for (int ks = 0; ks < 4; ks++) {
        uint32_t Ahi[2][4], Alo[2][4];
#pragma unroll
        for (int mt = 0; mt < 2; mt++) {
            int row = arow0 + mt * 16;
            uint32_t off = (uint32_t)(row * 128) +
                           ((uint32_t)((2 * ks + achk) ^ (row & 7)) << 4);
            ldsm4(Ahi[mt], sb + GX_HI + off);
            ldsm4(Alo[mt], sb + GX_LO + off);
        }
#pragma unroll
        for (int p = 0; p < 4; p++) {
            int nrow = p * 16 + brow;
            uint32_t off = (uint32_t)(nrow * 128) +
                           ((uint32_t)((2 * ks + bchk) ^ (nrow & 7)) << 4);
            uint32_t Bhi[4], Blo[4];
            ldsm4(Bhi, sb + GW_HI + off);
            ldsm4(Blo, sb + GW_LO + off);
#pragma unroll
            for (int mt = 0; mt < 2; mt++) {
                mma16816(D[mt][2 * p],     Ahi[mt], Bhi[0], Bhi[1]);
                mma16816(D[mt][2 * p],     Ahi[mt], Blo[0], Blo[1]);
                mma16816(D[mt][2 * p],     Alo[mt], Bhi[0], Bhi[1]);
                mma16816(D[mt][2 * p + 1], Ahi[mt], Bhi[2], Bhi[3]);
                mma16816(D[mt][2 * p + 1], Ahi[mt], Blo[2], Blo[3]);
                mma16816(D[mt][2 * p + 1], Alo[mt], Bhi[2], Bhi[3]);
            }
        }
    }

    const float* bsm = reinterpret_cast<const float*>(smem + G_BIAS);
    const int r0 = l >> 2, c0 = (l & 3) * 2;
#pragma unroll
    for (int mt = 0; mt < 2; mt++) {
#pragma unroll
        for (int half = 0; half < 2; half++) {
            int row = b0 + w * 32 + mt * 16 + r0 + half * 8;
            size_t base = ((size_t)row * FF + f) * EE;
            if (MODE == 1) {
                float* yrow = Yf + base;
#pragma unroll
                for (int nt = 0; nt < 8; nt++) {
                    float2 v = make_float2(D[mt][nt][2 * half], D[mt][nt][2 * half + 1]);
                    v.x += bsm[nt * 8 + c0];
                    v.y += bsm[nt * 8 + c0 + 1];
                    *reinterpret_cast<float2*>(yrow + nt * 8 + c0) = v;
                }
            } else {
#pragma unroll
                for (int nt = 0; nt < 8; nt++) {
                    float vx = D[mt][nt][2 * half], vy = D[mt][nt][2 * half + 1];
                    __nv_bfloat16 h0 = __float2bfloat16_rn(vx);
                    __nv_bfloat16 h1 = __float2bfloat16_rn(vy);
                    __nv_bfloat16 l0 = __float2bfloat16_rn(vx - __bfloat162float(h0));
                    __nv_bfloat16 l1 = __float2bfloat16_rn(vy - __bfloat162float(h1));
                    __nv_bfloat162 hp = __nv_bfloat162(h0, h1);
                    __nv_bfloat162 lp = __nv_bfloat162(l0, l1);
                    *reinterpret_cast<__nv_bfloat162*>(Yhi + base + nt * 8 + c0) = hp;
                    *reinterpret_cast<__nv_bfloat162*>(Ylo + base + nt * 8 + c0) = lp;
                }
            }
        }
    }
}

// ============================================================================
// Stage 2: aggregation via mma.sync bf16-split (staging rebuilt).
//   out[b,f,e] = sum_g G[b,f,g] * HO[b,g,e]   ([50x50]@[50x64], padded to 64)
// 2 batches/CTA, 256 threads. HO arrives pre-split bf16 -> pure uint4 copies.
// G staged with float2 loads. Zero-fill limited to pad regions. Occupancy 3.
// ============================================================================
#define AG_HI(lb) ((lb) * 32768 + 0)
#define AG_LO(lb) ((lb) * 32768 + 8192)
#define AH_HI(lb) ((lb) * 32768 + 16384)
#define AH_LO(lb) ((lb) * 32768 + 24576)
#define A_SMEM 65536

__global__ __launch_bounds__(256, 3) void aggr_mma(
    const float* __restrict__ Gm,
    const __nv_bfloat16* __restrict__ HOhi, const __nv_bfloat16* __restrict__ HOlo,
    float* __restrict__ out) {
    extern __shared__ char smem[];
    const uint32_t sb = smem_u32(smem);
    const int tid = threadIdx.x, w = tid >> 5, l = tid & 31;
    const int b0 = blockIdx.x * 2;

    // Zero pad areas: whole G regions (rows/cols >= 50 land there) ...
    const uint4 z4 = make_uint4(0, 0, 0, 0);
    for (int i = tid; i < 2048; i += 256) {        // 2 lb x 16KB of G (hi+lo)
        int lb = i >> 10;
        reinterpret_cast<uint4*>(smem + lb * 32768)[i & 1023] = z4;
    }
    // ... and HO rows 50..63 (hi+lo, both lb).
    for (int i = tid; i < 448; i += 256) {         // 2lb x 2half x 14rows x 8units
        int lb = i / 224, r = i - lb * 224;
        int half = r / 112, rr = r - half * 112;
        int g = 50 + (rr >> 3), u = rr & 7;
        uint32_t off = (uint32_t)(g * 128 + u * 16) ^ (((uint32_t)g & 7u) << 4);
        *reinterpret_cast<uint4*>(smem + AH_HI(lb) + half * 8192 + off) = z4;
    }
    __syncthreads();

    // Fill G: float2 loads, bf16 split, u32 stores.
    for (int i = tid; i < 2500; i += 256) {
        int lb = (i >= 1250);
        int r2 = i - lb * 1250;
        int fq = r2 / 25, g2 = r2 - fq * 25;
        float2 v = *reinterpret_cast<const float2*>(
            Gm + (size_t)(b0 + lb) * (FF * FF) + fq * FF + g2 * 2);
        __nv_bfloat16 h0 = __float2bfloat16_rn(v.x);
        __nv_bfloat16 h1 = __float2bfloat16_rn(v.y);
        __nv_bfloat16 l0 = __float2bfloat16_rn(v.x - __bfloat162float(h0));
        __nv_bfloat16 l1 = __float2bfloat16_rn(v.y - __bfloat162float(h1));
        __nv_bfloat162 hp = __nv_bfloat162(h0, h1);
        __nv_bfloat162 lp = __nv_bfloat162(l0, l1);
        uint32_t off = (uint32_t)(fq * 128 + g2 * 4) ^ (((uint32_t)fq & 7u) << 4);
        *reinterpret_cast<uint32_t*>(smem + AG_HI(lb) + off) =
            *reinterpret_cast<uint32_t*>(&hp);
        *reinterpret_cast<uint32_t*>(smem + AG_LO(lb) + off) =
            *reinterpret_cast<uint32_t*>(&lp);
    }
    // Fill HO: pure uint4 copies of pre-split bf16 (no conversion).
    for (int i = tid; i < 1600; i += 256) {
        int half = (i >= 800);
        int r = i - half * 800;
        int lb = (r >= 400);
        int rr = r - lb * 400;
        int g = rr >> 3, u = rr & 7;
        const __nv_bfloat16* src = (half ? HOlo : HOhi) +
            ((size_t)(b0 + lb) * FF + g) * EE + u * 8;
        uint32_t off = (uint32_t)(g * 128 + u * 16) ^ (((uint32_t)g & 7u) << 4);
        *reinterpret_cast<uint4*>(smem + AH_HI(lb) + half * 8192 + off) =
            *reinterpret_cast<const uint4*>(src);
    }
    __syncthreads();

    const int lb = w >> 2, wq = w & 3;
    const int arow  = wq * 16 + (l & 15);
    const int achk  = l >> 4;
    const int bkrow = (l & 7) + (((l >> 3) & 1) << 3);
    const int bchk  = l >> 4;

    float D[8][4] = {};

#pragma unroll
    for (int ks = 0; ks < 4; ks++) {
        uint32_t Ahi[4], Alo[4];
        uint32_t aoff = (uint32_t)(arow * 128) +
                        ((uint32_t)((2 * ks + achk) ^ (arow & 7)) << 4);
        ldsm4(Ahi, sb + AG_HI(lb) + aoff);
        ldsm4(Alo, sb + AG_LO(lb) + aoff);
#pragma unroll
        for (int p = 0; p < 4; p++) {
            int krow = ks * 16 + bkrow;
            uint32_t boff = (uint32_t)(krow * 128) +
                            ((uint32_t)((2 * p + bchk) ^ (krow & 7)) << 4);
            uint32_t Bhi[4], Blo[4];
            ldsm4t(Bhi, sb + AH_HI(lb) + boff);
            ldsm4t(Blo, sb + AH_LO(lb) + boff);
            mma16816(D[2 * p],     Ahi, Bhi[0], Bhi[1]);
            mma16816(D[2 * p],     Ahi, Blo[0], Blo[1]);
            mma16816(D[2 * p],     Alo, Bhi[0], Bhi[1]);
            mma16816(D[2 * p + 1], Ahi, Bhi[2], Bhi[3]);
            mma16816(D[2 * p + 1], Ahi, Blo[2], Blo[3]);
            mma16816(D[2 * p + 1], Alo, Bhi[2], Bhi[3]);
        }
    }

    const int r0 = l >> 2, c0 = (l & 3) * 2;
#pragma unroll
    for (int half = 0; half < 2; half++) {
        int frow = wq * 16 + r0 + half * 8;
        if (frow < FF) {
            float* orow = out + (size_t)(b0 + lb) * (FF * EE) + frow * EE;
#pragma unroll
            for (int nt = 0; nt < 8; nt++)
                *reinterpret_cast<float2*>(orow + nt * 8 + c0) =
                    make_float2(D[nt][2 * half], D[nt][2 * half + 1]);
        }
    }
}

extern "C" void kernel_launch(void* const* d_in, const int* in_sizes, int n_in,
                              void* d_out, int out_size) {
    const float* g     = (const float*)d_in[0];   // [B,F,F]
    const float* h     = (const float*)d_in[1];   // [B,F,E]
    const float* W_in  = (const float*)d_in[2];   // [F,E,E]
    const float* W_out = (const float*)d_in[3];   // [F,E,E]
    const float* bias  = (const float*)d_in[4];   // [E]
    float* out = (float*)d_out;                   // [B,F,E]

    __nv_bfloat16 *hohi = nullptr, *holo = nullptr;
    cudaGetSymbolAddress((void**)&hohi, g_ho_hi);
    cudaGetSymbolAddress((void**)&holo, g_ho_lo);

    cudaFuncSetAttribute((const void*)field_gemm_mma<0>,
                         cudaFuncAttributeMaxDynamicSharedMemorySize, G_SMEM);
    cudaFuncSetAttribute((const void*)field_gemm_mma<1>,
                         cudaFuncAttributeMaxDynamicSharedMemorySize, G_SMEM);
    cudaFuncSetAttribute((const void*)aggr_mma,
                         cudaFuncAttributeMaxDynamicSharedMemorySize, A_SMEM);

    // Stage 1: ho(hi/lo) = split( einsum('fij,bfj->bfi', W_out, h) )
    field_gemm_mma<0><<<dim3(BB / 128, FF), 128, G_SMEM>>>(
        h, W_out, nullptr, nullptr, hohi, holo);
    // Stage 2: out = einsum('bfg,bge->bfe', g, ho)
    aggr_mma<<<BB / 2, 256, A_SMEM>>>(g, hohi, holo, out);
    // Stage 3 (in-place): out = einsum('fij,bfj->bfi', W_in, out) + bias
    field_gemm_mma<1><<<dim3(BB / 128, FF), 128, G_SMEM>>>(
        out, W_in, bias, out, nullptr, nullptr);
}

// round 7
// speedup vs baseline: 1.5072x; 1.1019x over previous
#include <cuda_runtime.h>
#include <cuda_bf16.h>
#include <cstdint>

#define BB 16384
#define FF 50
#define EE 64

// Stage-1 intermediate h_out, stored as bf16 hi/lo split (105MB each).
__device__ __nv_bfloat16 g_ho_hi[(size_t)BB * FF * EE];
__device__ __nv_bfloat16 g_ho_lo[(size_t)BB * FF * EE];

// ======================= helpers =======================
__device__ __forceinline__ uint32_t smem_u32(const void* p) {
    uint32_t a;
    asm("{ .reg .u64 t; cvta.to.shared.u64 t, %1; cvt.u32.u64 %0, t; }"
        : "=r"(a) : "l"(p));
    return a;
}
__device__ __forceinline__ void ldsm4(uint32_t* r, uint32_t a) {
    asm volatile("ldmatrix.sync.aligned.m8n8.x4.shared.b16 {%0,%1,%2,%3}, [%4];"
        : "=r"(r[0]), "=r"(r[1]), "=r"(r[2]), "=r"(r[3]) : "r"(a));
}
__device__ __forceinline__ void ldsm4t(uint32_t* r, uint32_t a) {
    asm volatile("ldmatrix.sync.aligned.m8n8.x4.trans.shared.b16 {%0,%1,%2,%3}, [%4];"
        : "=r"(r[0]), "=r"(r[1]), "=r"(r[2]), "=r"(r[3]) : "r"(a));
}
__device__ __forceinline__ void mma16816(float* d, const uint32_t* a,
                                         uint32_t b0, uint32_t b1) {
    asm volatile(
        "mma.sync.aligned.m16n8k16.row.col.f32.bf16.bf16.f32 "
        "{%0,%1,%2,%3}, {%4,%5,%6,%7}, {%8,%9}, {%0,%1,%2,%3};"
        : "+f"(d[0]), "+f"(d[1]), "+f"(d[2]), "+f"(d[3])
        : "r"(a[0]), "r"(a[1]), "r"(a[2]), "r"(a[3]), "r"(b0), "r"(b1));
}

// Convert float4 -> bf16 hi/lo, store into [row][64]bf16 tile (128B rows,
// XOR-(row&7)<<4 permuted so ldmatrix over 8 consecutive rows is conflict-free).
__device__ __forceinline__ void split_store4(char* hiB, char* loB, int row, int c4,
                                             float4 v) {
    __nv_bfloat16 h0 = __float2bfloat16_rn(v.x);
    __nv_bfloat16 h1 = __float2bfloat16_rn(v.y);
    __nv_bfloat16 h2 = __float2bfloat16_rn(v.z);
    __nv_bfloat16 h3 = __float2bfloat16_rn(v.w);
    __nv_bfloat16 l0 = __float2bfloat16_rn(v.x - __bfloat162float(h0));
    __nv_bfloat16 l1 = __float2bfloat16_rn(v.y - __bfloat162float(h1));
    __nv_bfloat16 l2 = __float2bfloat16_rn(v.z - __bfloat162float(h2));
    __nv_bfloat16 l3 = __float2bfloat16_rn(v.w - __bfloat162float(h3));
    __nv_bfloat162 hp0 = __nv_bfloat162(h0, h1), hp1 = __nv_bfloat162(h2, h3);
    __nv_bfloat162 lp0 = __nv_bfloat162(l0, l1), lp1 = __nv_bfloat162(l2, l3);
    uint32_t byte0 = (uint32_t)(row * 128 + c4 * 8);
    uint32_t sw = byte0 ^ (((uint32_t)row & 7u) << 4);
    *reinterpret_cast<uint32_t*>(hiB + sw)     = *reinterpret_cast<uint32_t*>(&hp0);
    *reinterpret_cast<uint32_t*>(hiB + sw + 4) = *reinterpret_cast<uint32_t*>(&hp1);
    *reinterpret_cast<uint32_t*>(loB + sw)     = *reinterpret_cast<uint32_t*>(&lp0);
    *reinterpret_cast<uint32_t*>(loB + sw + 4) = *reinterpret_cast<uint32_t*>(&lp1);
}

// ============================================================================
// Stage 1 / Stage 3: per-field GEMM via mma.sync bf16-split.
//   Y[b,i] = sum_j X[b,j] * W[f,i,j]
// MODE 0: write bf16 hi/lo split. MODE 1: write fp32 + bias, IN-PLACE on out.
// Grid (B/128, F), 128 threads (4 warps). CTA tile 128b x 64i, K=64.
// Epilogue stages D through smem (swizzled) for fully coalesced gmem stores.
// ============================================================================
#define GX_HI 0
#define GX_LO 16384
#define GW_HI 32768
#define GW_LO 40960
#define G_BIAS 49152
#define G_SMEM 49664

template <int MODE>
__global__ __launch_bounds__(128, 4) void field_gemm_mma(
    const float* __restrict__ X, const float* __restrict__ W,
    const float* __restrict__ bias, float* __restrict__ Yf,
    __nv_bfloat16* __restrict__ Yhi, __nv_bfloat16* __restrict__ Ylo) {
    extern __shared__ char smem[];
    const uint32_t sb = smem_u32(smem);
    const int tid = threadIdx.x, w = tid >> 5, l = tid & 31;
    const int f = blockIdx.y, b0 = blockIdx.x * 128;

    if (MODE == 1 && tid < 16)
        reinterpret_cast<float4*>(smem + G_BIAS)[tid] =
            reinterpret_cast<const float4*>(bias)[tid];

    // Stage X tile (128 x 64 fp32) -> bf16 hi/lo
    const float* Xb = X + (size_t)b0 * (FF * EE) + (size_t)f * EE;
#pragma unroll
    for (int t = 0; t < 16; t++) {
        int idx = tid + t * 128;
        int b = idx >> 4, c4 = idx & 15;
        float4 v = *reinterpret_cast<const float4*>(Xb + (size_t)b * (FF * EE) + c4 * 4);
        split_store4(smem + GX_HI, smem + GX_LO, b, c4, v);
    }
    // Stage W[f] (64 x 64): rows are n=i, k=j contiguous
    const float* Wf = W + (size_t)f * EE * EE;
#pragma unroll
    for (int t = 0; t < 8; t++) {
        int idx = tid + t * 128;
        int n = idx >> 4, c4 = idx & 15;
        float4 v = *reinterpret_cast<const float4*>(Wf + n * EE + c4 * 4);
        split_store4(smem + GW_HI, smem + GW_LO, n, c4, v);
    }
    __syncthreads();

    const int arow0 = w * 32 + (l & 15);
    const int achk  = l >> 4;
    const int brow  = (l & 7) + ((l >> 4) << 3);
    const int bchk  = (l >> 3) & 1;

    float D[2][8][4] = {};

#pragma unroll
    for (int ks = 0; ks < 4; ks++) {
        uint32_t Ahi[2][4], Alo[2][4];
#pragma unroll
        for (int mt = 0; mt < 2; mt++) {
            int row = arow0 + mt * 16;
            uint32_t off = (uint32_t)(row * 128) +
                           ((uint32_t)((2 * ks + achk) ^ (row & 7)) << 4);
            ldsm4(Ahi[mt], sb + GX_HI + off);
            ldsm4(Alo[mt], sb + GX_LO + off);
        }
#pragma unroll
        for (int p = 0; p < 4; p++) {
            int nrow = p * 16 + brow;
            uint32_t off = (uint32_t)(nrow * 128) +
                           ((uint32_t)((2 * ks + bchk) ^ (nrow & 7)) << 4);
            uint32_t Bhi[4], Blo[4];
            ldsm4(Bhi, sb + GW_HI + off);
            ldsm4(Blo, sb + GW_LO + off);
#pragma unroll
            for (int mt = 0; mt < 2; mt++) {
                mma16816(D[mt][2 * p],     Ahi[mt], Bhi[0], Bhi[1]);
                mma16816(D[mt][2 * p],     Ahi[mt], Blo[0], Blo[1]);
                mma16816(D[mt][2 * p],     Alo[mt], Bhi[0], Bhi[1]);
                mma16816(D[mt][2 * p + 1], Ahi[mt], Bhi[2], Bhi[3]);
                mma16816(D[mt][2 * p + 1], Ahi[mt], Blo[2], Blo[3]);
                mma16816(D[mt][2 * p + 1], Alo[mt], Bhi[2], Bhi[3]);
            }
        }
    }

    // -------- epilogue: stage through smem, then coalesced gmem stores ------
    __syncthreads();   // done reading X/W smem; reuse [0, 32KB)

    const int r0 = l >> 2, c0 = (l & 3) * 2;
    if (MODE == 0) {
        // smem: hi tile [128][128B] at 0, lo tile at 16384; swizzled by row.
#pragma unroll
        for (int mt = 0; mt < 2; mt++)
#pragma unroll
            for (int half = 0; half < 2; half++) {
                int rl = w * 32 + mt * 16 + half * 8 + r0;
                uint32_t rsw = ((uint32_t)rl & 7u) << 4;
#pragma unroll
                for (int nt = 0; nt < 8; nt++) {
                    float vx = D[mt][nt][2 * half], vy = D[mt][nt][2 * half + 1];
                    __nv_bfloat16 h0 = __float2bfloat16_rn(vx);
                    __nv_bfloat16 h1 = __float2bfloat16_rn(vy);
                    __nv_bfloat16 l0 = __float2bfloat16_rn(vx - __bfloat162float(h0));
                    __nv_bfloat16 l1 = __float2bfloat16_rn(vy - __bfloat162float(h1));
                    __nv_bfloat162 hp = __nv_bfloat162(h0, h1);
                    __nv_bfloat162 lp = __nv_bfloat162(l0, l1);
                    uint32_t off = (uint32_t)(rl * 128) +
                                   (((uint32_t)((nt * 8 + c0) * 2)) ^ rsw);
                    *reinterpret_cast<uint32_t*>(smem + off) =
                        *reinterpret_cast<uint32_t*>(&hp);
                    *reinterpret_cast<uint32_t*>(smem + 16384 + off) =
                        *reinterpret_cast<uint32_t*>(&lp);
                }
            }
        __syncthreads();
        // write out: each warp its 32 rows, 128B contiguous per row
#pragma unroll
        for (int it = 0; it < 8; it++) {
            int rl = w * 32 + it * 4 + (l >> 3);
            int u  = l & 7;
            uint32_t off = (uint32_t)(rl * 128) +
                           (((uint32_t)(u * 16)) ^ (((uint32_t)rl & 7u) << 4));
            uint4 vhi = *reinterpret_cast<const uint4*>(smem + off);
            uint4 vlo = *reinterpret_cast<const uint4*>(smem + 16384 + off);
            size_t base = ((size_t)(b0 + rl) * FF + f) * EE + u * 8;
            *reinterpret_cast<uint4*>(Yhi + base) = vhi;
            *reinterpret_cast<uint4*>(Ylo + base) = vlo;
        }
    } else {
        // smem: fp32 tile [128][256B] at 0, swizzled by row.
#pragma unroll
        for (int mt = 0; mt < 2; mt++)
#pragma unroll
            for (int half = 0; half < 2; half++) {
                int rl = w * 32 + mt * 16 + half * 8 + r0;
                uint32_t rsw = ((uint32_t)rl & 7u) << 4;
#pragma unroll
                for (int nt = 0; nt < 8; nt++) {
                    float2 v = make_float2(D[mt][nt][2 * half], D[mt][nt][2 * half + 1]);
                    uint32_t off = (uint32_t)(rl * 256) +
                                   (((uint32_t)((nt * 8 + c0) * 4)) ^ rsw);
                    *reinterpret_cast<float2*>(smem + off) = v;
                }
            }
        __syncthreads();
        const float* bsm = reinterpret_cast<const float*>(smem + G_BIAS);
#pragma unroll
        for (int it = 0; it < 16; it++) {
            int rl = w * 32 + it * 2 + (l >> 4);
            int u  = l & 15;
            uint32_t off = (uint32_t)(rl * 256) +
                           (((uint32_t)(u * 16)) ^ (((uint32_t)rl & 7u) << 4));
            float4 v = *reinterpret_cast<const float4*>(smem + off);
            v.x += bsm[u * 4 + 0];
            v.y += bsm[u * 4 + 1];
            v.z += bsm[u * 4 + 2];
            v.w += bsm[u * 4 + 3];
            size_t base = ((size_t)(b0 + rl) * FF + f) * EE + u * 4;
            *reinterpret_cast<float4*>(Yf + base) = v;
        }
    }
}

// ============================================================================
// Stage 2: aggregation via mma.sync bf16-split.
//   out[b,f,e] = sum_g G[b,f,g] * HO[b,g,e]   ([50x50]@[50x64], padded to 64)
// 1 batch/CTA, 128 threads, 32KB smem -> occupancy 7 (latency-bound staging
// hidden by CTA overlap). Warp wq computes m16 (rows 16wq..16wq+15) x n64.
// ============================================================================
#define AG_HI 0
#define AG_LO 8192
#define AH_HI 16384
#define AH_LO 24576
#define A_SMEM 32768

__global__ __launch_bounds__(128, 7) void aggr_mma(
    const float* __restrict__ Gm,
    const __nv_bfloat16* __restrict__ HOhi, const __nv_bfloat16* __restrict__ HOlo,
    float* __restrict__ out) {
    extern __shared__ char smem[];
    const uint32_t sb = smem_u32(smem);
    const int tid = threadIdx.x, w = tid >> 5, l = tid & 31;
    const int b = blockIdx.x;

    const uint4 z4 = make_uint4(0, 0, 0, 0);
    // Zero G regions (16KB: rows/cols >= 50 must be 0)
    for (int i = tid; i < 1024; i += 128)
        reinterpret_cast<uint4*>(smem)[i] = z4;
    // Zero HO pad rows 50..63 (hi+lo)
    for (int i = tid; i < 224; i += 128) {
        int half = i / 112, rr = i - half * 112;
        int g = 50 + (rr >> 3), u = rr & 7;
        uint32_t off = (uint32_t)(g * 128 + u * 16) ^ (((uint32_t)g & 7u) << 4);
        *reinterpret_cast<uint4*>(smem + AH_HI + half * 8192 + off) = z4;
    }
    __syncthreads();

    // Fill G: float2 loads, bf16 split, u32 stores.
    for (int i = tid; i < 1250; i += 128) {
        int fq = i / 25, g2 = i - fq * 25;
        float2 v = *reinterpret_cast<const float2*>(
            Gm + (size_t)b * (FF * FF) + fq * FF + g2 * 2);
        __nv_bfloat16 h0 = __float2bfloat16_rn(v.x);
        __nv_bfloat16 h1 = __float2bfloat16_rn(v.y);
        __nv_bfloat16 l0 = __float2bfloat16_rn(v.x - __bfloat162float(h0));
        __nv_bfloat16 l1 = __float2bfloat16_rn(v.y - __bfloat162float(h1));
        __nv_bfloat162 hp = __nv_bfloat162(h0, h1);
        __nv_bfloat162 lp = __nv_bfloat162(l0, l1);
        uint32_t off = (uint32_t)(fq * 128 + g2 * 4) ^ (((uint32_t)fq & 7u) << 4);
        *reinterpret_cast<uint32_t*>(smem + AG_HI + off) =
            *reinterpret_cast<uint32_t*>(&hp);
        *reinterpret_cast<uint32_t*>(smem + AG_LO + off) =
            *reinterpret_cast<uint32_t*>(&lp);
    }
    // Fill HO: pure uint4 copies of pre-split bf16 (no conversion).
    for (int i = tid; i < 800; i += 128) {
        int half = (i >= 400);
        int rr = i - half * 400;
        int g = rr >> 3, u = rr & 7;
        const __nv_bfloat16* src = (half ? HOlo : HOhi) +
            ((size_t)b * FF + g) * EE + u * 8;
        uint32_t off = (uint32_t)(g * 128 + u * 16) ^ (((uint32_t)g & 7u) << 4);
        *reinterpret_cast<uint4*>(smem + AH_HI + half * 8192 + off) =
            *reinterpret_cast<const uint4*>(src);
    }
    __syncthreads();

    const int arow  = w * 16 + (l & 15);
    const int achk  = l >> 4;
    const int bkrow = (l & 7) + (((l >> 3) & 1) << 3);
    const int bchk  = l >> 4;

    float D[8][4] = {};

#pragma unroll
    for (int ks = 0; ks < 4; ks++) {
        uint32_t Ahi[4], Alo[4];
        uint32_t aoff = (uint32_t)(arow * 128) +
                        ((uint32_t)((2 * ks + achk) ^ (arow & 7)) << 4);
        ldsm4(Ahi, sb + AG_HI + aoff);
        ldsm4(Alo, sb + AG_LO + aoff);
#pragma unroll
        for (int p = 0; p < 4; p++) {
            int krow = ks * 16 + bkrow;
            uint32_t boff = (uint32_t)(krow * 128) +
                            ((uint32_t)((2 * p + bchk) ^ (krow & 7)) << 4);
            uint32_t Bhi[4], Blo[4];
            ldsm4t(Bhi, sb + AH_HI + boff);
            ldsm4t(Blo, sb + AH_LO + boff);
            mma16816(D[2 * p],     Ahi, Bhi[0], Bhi[1]);
            mma16816(D[2 * p],     Ahi, Blo[0], Blo[1]);
            mma16816(D[2 * p],     Alo, Bhi[0], Bhi[1]);
            mma16816(D[2 * p + 1], Ahi, Bhi[2], Bhi[3]);
            mma16816(D[2 * p + 1], Ahi, Blo[2], Blo[3]);
            mma16816(D[2 * p + 1], Alo, Bhi[2], Bhi[3]);
        }
    }

    const int r0 = l >> 2, c0 = (l & 3) * 2;
#pragma unroll
    for (int half = 0; half < 2; half++) {
        int frow = w * 16 + r0 + half * 8;
        if (frow < FF) {
            float* orow = out + (size_t)b * (FF * EE) + frow * EE;
#pragma unroll
            for (int nt = 0; nt < 8; nt++)
                *reinterpret_cast<float2*>(orow + nt * 8 + c0) =
                    make_float2(D[nt][2 * half], D[nt][2 * half + 1]);
        }
    }
}

extern "C" void kernel_launch(void* const* d_in, const int* in_sizes, int n_in,
                              void* d_out, int out_size) {
    const float* g     = (const float*)d_in[0];   // [B,F,F]
    const float* h     = (const float*)d_in[1];   // [B,F,E]
    const float* W_in  = (const float*)d_in[2];   // [F,E,E]
    const float* W_out = (const float*)d_in[3];   // [F,E,E]
    const float* bias  = (const float*)d_in[4];   // [E]
    float* out = (float*)d_out;                   // [B,F,E]

    __nv_bfloat16 *hohi = nullptr, *holo = nullptr;
    cudaGetSymbolAddress((void**)&hohi, g_ho_hi);
    cudaGetSymbolAddress((void**)&holo, g_ho_lo);

    cudaFuncSetAttribute((const void*)field_gemm_mma<0>,
                         cudaFuncAttributeMaxDynamicSharedMemorySize, G_SMEM);
    cudaFuncSetAttribute((const void*)field_gemm_mma<1>,
                         cudaFuncAttributeMaxDynamicSharedMemorySize, G_SMEM);
    cudaFuncSetAttribute((const void*)aggr_mma,
                         cudaFuncAttributeMaxDynamicSharedMemorySize, A_SMEM);

    // Stage 1: ho(hi/lo) = split( einsum('fij,bfj->bfi', W_out, h) )
    field_gemm_mma<0><<<dim3(BB / 128, FF), 128, G_SMEM>>>(
        h, W_out, nullptr, nullptr, hohi, holo);
    // Stage 2: out = einsum('bfg,bge->bfe', g, ho)
    aggr_mma<<<BB, 128, A_SMEM>>>(g, hohi, holo, out);
    // Stage 3 (in-place): out = einsum('fij,bfj->bfi', W_in, out) + bias
    field_gemm_mma<1><<<dim3(BB / 128, FF), 128, G_SMEM>>>(
        out, W_in, bias, out, nullptr, nullptr);
}